// round 2
// baseline (speedup 1.0000x reference)
#include <cuda_runtime.h>
#include <cuda_bf16.h>
#include <cstdint>

// Problem constants
#define BATCH   64
#define CH      256      // C_IN == C_OUT
#define HH      32
#define WW      32
#define NBRANCH 4

// Tiling
#define CO_T    64       // output channels per CTA
#define RT      8        // output rows per CTA (full 32-col width)
#define KC      8        // input channels staged per chunk
#define NTHREADS 256

// SMEM layouts
// X tile: KC x (RT+2) x (WW+2) = 8 x 10 x 34, linear, stride 34
#define XS_CI   340      // 10*34
#define XS_ELEMS (KC*XS_CI)          // 2720
// W tile: [ci][k] rows of 64 co, padded stride 68 (16B-aligned, spreads banks)
#define WS_STRIDE 68
#define WS_ELEMS (KC*9*WS_STRIDE)    // 4896

__global__ __launch_bounds__(NTHREADS, 2)
void mixed_conv3x3_kernel(const float* __restrict__ x,
                          const int*   __restrict__ arc,
                          const float* __restrict__ Wt,   // [NB, CO, CI, 3, 3]
                          const float* __restrict__ bias, // [NB, CO]
                          float*       __restrict__ out)  // [B, CO, H, W]
{
    __shared__ __align__(16) float sX[XS_ELEMS];
    __shared__ __align__(16) float sW[WS_ELEMS];

    const int t   = threadIdx.x;
    const int bb  = blockIdx.z;
    const int oc0 = blockIdx.y * CO_T;
    const int h0  = blockIdx.x * RT;

    const int a = arc[bb];                 // branch for this sample (0..3)

    // Weight base for this (branch, oc tile): W[a][oc0 + oc][ci][k]
    const float* Wbase = Wt + ((size_t)a * CH + oc0) * (size_t)(CH * 9);

    float acc[8][8];
#pragma unroll
    for (int i = 0; i < 8; i++)
#pragma unroll
        for (int j = 0; j < 8; j++)
            acc[i][j] = 0.0f;

    const int col    = t & 31;        // output column handled by this thread
    const int oc_grp = (t >> 5) << 3; // first of 8 output channels for this thread

    // Precompute staging coordinates for the X loop (each thread touches
    // XS_ELEMS/NTHREADS = 10.625 -> 11 strided slots; decode once, step after).
    for (int ci0 = 0; ci0 < CH; ci0 += KC) {
        // ---- stage X chunk: [KC][10][34] with zero halo ----
        int idx = t;
        int ci  = idx / XS_CI;
        int rem = idx - ci * XS_CI;
        int r   = rem / 34;
        int c   = rem - r * 34;
        while (idx < XS_ELEMS) {
            int gr  = h0 - 1 + r;
            int gc  = c - 1;
            float v = 0.0f;
            if ((unsigned)gr < (unsigned)HH && (unsigned)gc < (unsigned)WW)
                v = x[(((size_t)bb * CH + ci0 + ci) * HH + gr) * WW + gc];
            sX[idx] = v;
            idx += NTHREADS;
            // step (r,c,ci) forward by NTHREADS = 7*34 + 18
            c += 18; r += 7;
            if (c >= 34) { c -= 34; r += 1; }
            if (r >= 10) { r -= 10; ci += 1; }
        }
        // ---- stage W chunk transposed: sW[(ci*9+k)*68 + oc] ----
        for (int widx = t; widx < CO_T * KC * 9; widx += NTHREADS) {
            int oc   = widx / (KC * 9);
            int wrem = widx - oc * (KC * 9);      // wrem = ci*9 + k
            float v = Wbase[(size_t)oc * (CH * 9) + ci0 * 9 + wrem];
            sW[wrem * WS_STRIDE + oc] = v;
        }
        __syncthreads();

        // ---- compute: per (ci,k): 2x LDS.128 (W bcast) + 8x LDS.32 (X) -> 64 FFMA ----
        const float* xs0 = &sX[col];
        const float* ws0 = &sW[oc_grp];
#pragma unroll 1
        for (int cc = 0; cc < KC; cc++) {
            const float* xs = xs0 + cc * XS_CI;
            const float* ws = ws0 + cc * (9 * WS_STRIDE);
#pragma unroll
            for (int k = 0; k < 9; k++) {
                const int kh = k / 3;
                const int kw = k - kh * 3;
                float4 wa = *reinterpret_cast<const float4*>(ws + k * WS_STRIDE);
                float4 wb = *reinterpret_cast<const float4*>(ws + k * WS_STRIDE + 4);
                float w[8] = {wa.x, wa.y, wa.z, wa.w, wb.x, wb.y, wb.z, wb.w};
#pragma unroll
                for (int j = 0; j < 8; j++) {
                    float xv = xs[(j + kh) * 34 + kw];
#pragma unroll
                    for (int i = 0; i < 8; i++)
                        acc[i][j] = fmaf(w[i], xv, acc[i][j]);
                }
            }
        }
        __syncthreads();
    }

    // ---- epilogue: add bias, store (coalesced along columns) ----
#pragma unroll
    for (int i = 0; i < 8; i++) {
        float bi = bias[a * CH + oc0 + oc_grp + i];
        size_t obase = (((size_t)bb * CH + oc0 + oc_grp + i) * HH + h0) * WW + col;
#pragma unroll
        for (int j = 0; j < 8; j++)
            out[obase + (size_t)j * WW] = acc[i][j] + bi;
    }
}

extern "C" void kernel_launch(void* const* d_in, const int* in_sizes, int n_in,
                              void* d_out, int out_size)
{
    const float* x    = (const float*)d_in[0];  // [64,256,32,32]
    const int*   arc  = (const int*)  d_in[1];  // [64]
    const float* Wt   = (const float*)d_in[2];  // [4,256,256,3,3]
    const float* bias = (const float*)d_in[3];  // [4,256]
    float* out = (float*)d_out;                 // [64,256,32,32]

    dim3 grid(HH / RT, CH / CO_T, BATCH);       // (4, 4, 64)
    dim3 block(NTHREADS);
    mixed_conv3x3_kernel<<<grid, block>>>(x, arc, Wt, bias, out);
}

// round 6
// speedup vs baseline: 3.2080x; 3.2080x over previous
#include <cuda_runtime.h>
#include <cuda_fp16.h>
#include <cstdint>

#define BATCH   64
#define CH      256
#define HH      32
#define WW      32
#define NCHUNK  16        // 16 ci-chunks of 16

#define THREADS 512
#define SP_ROWS 8         // M = 256 spatial (8 rows x 32 cols)
#define CO_TILE 128       // N

// SMEM stage layout
#define SX_SLOT   48                      // bytes per (row',col') slot (16 ci fp16 in first 32B)
#define SX_BYTES  (10 * 34 * SX_SLOT)     // 16320
#define SW_BYTES  (9 * 128 * SX_SLOT)     // 55296  (tap-major, 48B/co slot)
#define STAGE_BYTES (SX_BYTES + SW_BYTES) // 71616
#define SMEM_TOTAL  (2 * STAGE_BYTES)     // 143232
#define OUT_STR   272                     // epilogue s_out stride (floats)

// Pre-transposed fp16 weights: [branch][ci_chunk 16][tap 9][co 256][ci16]
static __device__ __half g_wt[4u * 16 * 9 * 256 * 16];

static __device__ __forceinline__ uint32_t s2u(const void* p) {
    return (uint32_t)__cvta_generic_to_shared(p);
}

#define LDSM4(r0, r1, r2, r3, addr)                                         \
    asm volatile("ldmatrix.sync.aligned.m8n8.x4.shared.b16 "                \
                 "{%0,%1,%2,%3}, [%4];"                                     \
                 : "=r"(r0), "=r"(r1), "=r"(r2), "=r"(r3) : "r"(addr))

#define MMA16816(c, a0, a1, a2, a3, b0, b1)                                 \
    asm volatile("mma.sync.aligned.m16n8k16.row.col.f32.f16.f16.f32 "       \
                 "{%0,%1,%2,%3}, {%4,%5,%6,%7}, {%8,%9}, {%0,%1,%2,%3};"    \
                 : "+f"((c)[0]), "+f"((c)[1]), "+f"((c)[2]), "+f"((c)[3])   \
                 : "r"(a0), "r"(a1), "r"(a2), "r"(a3), "r"(b0), "r"(b1))

// ---------------------------------------------------------------------------
// Weight transpose + fp32->fp16: W[a][co][ci][tap] -> g_wt[a][ci>>4][tap][co][ci&15]
// ---------------------------------------------------------------------------
__global__ __launch_bounds__(256)
void wt_transpose_kernel(const float* __restrict__ Wt)
{
    const int tid = blockIdx.x * 256 + threadIdx.x;   // 262144 total
    const int a   = tid >> 16;
    const int co  = (tid >> 8) & 255;
    const int ci  = tid & 255;
    const float* src = Wt + ((size_t)(a * 256 + co) * 256 + ci) * 9;
    const int kc   = ci >> 4;
    const int ci16 = ci & 15;
#pragma unroll
    for (int tap = 0; tap < 9; ++tap) {
        g_wt[((((size_t)a * 16 + kc) * 9 + tap) * 256 + co) * 16 + ci16] =
            __float2half_rn(src[tap]);
    }
}

// ---------------------------------------------------------------------------
// Main kernel: implicit conv as tap-decomposed fp16 HMMA GEMM
// ---------------------------------------------------------------------------
__global__ __launch_bounds__(THREADS, 1)
void conv_mma_kernel(const float* __restrict__ x,
                     const int*   __restrict__ arc,
                     const float* __restrict__ bias,
                     float*       __restrict__ out)
{
    extern __shared__ __align__(16) char smem[];

    const int t    = threadIdx.x;
    const int lane = t & 31;
    const int wid  = t >> 5;          // 0..15
    const int mw   = wid >> 1;        // 0..7  (spatial row r)
    const int nw   = wid & 1;         // 0..1  (co half)

    const int bb  = blockIdx.z;
    const int co0 = blockIdx.y * CO_TILE;
    const int h0  = blockIdx.x * SP_ROWS;
    const int a   = arc[bb];

    const uint32_t smem_u = s2u(smem);

    float acc[2][8][4];
#pragma unroll
    for (int mt = 0; mt < 2; ++mt)
#pragma unroll
        for (int nt = 0; nt < 8; ++nt)
#pragma unroll
            for (int k = 0; k < 4; ++k)
                acc[mt][nt][k] = 0.0f;

    // per-lane ldmatrix offsets
    const uint32_t laneA = (uint32_t)((lane & 15) * SX_SLOT + (lane >> 4) * 16);
    const uint32_t laneB = (uint32_t)(((((lane >> 4) & 1) * 8 + (lane & 7)) + nw * 64) * SX_SLOT
                                      + ((lane >> 3) & 1) * 16);

    const float* xbase = x + (size_t)bb * CH * (HH * WW);

    for (int it = 0; it < NCHUNK; ++it) {
        const int s = it & 1;
        const uint32_t stBase = (uint32_t)(s * STAGE_BYTES);
        const int ci0 = it << 4;

        // ---- stage X halo tile: s_x[row' 0..9][col' 0..33][ci 0..15] fp16 ----
        {
            char* sx = smem + stBase;
#pragma unroll 1
            for (int e = t; e < 5440; e += THREADS) {
                const int ci   = e / 340;
                const int rem  = e - ci * 340;
                const int row  = rem / 34;
                const int col  = rem - row * 34;
                const int gr   = h0 + row - 1;
                const int gc   = col - 1;
                float v = 0.0f;
                if ((unsigned)gr < (unsigned)HH && (unsigned)gc < (unsigned)WW)
                    v = xbase[(size_t)(ci0 + ci) * (HH * WW) + (gr << 5) + gc];
                *reinterpret_cast<__half*>(sx + (row * 34 + col) * SX_SLOT + ci * 2) =
                    __float2half_rn(v);
            }
        }
        // ---- stage W: s_w[tap][co][ci16], 32B coalesced slots from g_wt ----
        {
            char* sw = smem + stBase + SX_BYTES;
            const __half* wsrc =
                g_wt + (((size_t)a * 16 + it) * 9) * 256 * 16 + (size_t)co0 * 16;
#pragma unroll 1
            for (int slot = t; slot < 9 * 128; slot += THREADS) {
                const int tap = slot >> 7;
                const int co  = slot & 127;
                const uint4* src = reinterpret_cast<const uint4*>(
                    wsrc + ((size_t)tap * 256 + co) * 16);
                uint4 v0 = src[0];
                uint4 v1 = src[1];
                uint4* dst = reinterpret_cast<uint4*>(sw + (tap * 128 + co) * SX_SLOT);
                dst[0] = v0;
                dst[1] = v1;
            }
        }

        __syncthreads();

        // ---- compute: 9 taps x (k16 = 16 ci) ----
        const uint32_t sx = smem_u + stBase;
        const uint32_t sw = smem_u + stBase + SX_BYTES;
#pragma unroll
        for (int tap = 0; tap < 9; ++tap) {
            const int dh = tap / 3;
            const int dw = tap - 3 * dh;
            const uint32_t aAddr = sx + (uint32_t)(((mw + dh) * 34 + dw) * SX_SLOT) + laneA;
            uint32_t a0, a1, a2, a3, a4, a5, a6, a7;
            LDSM4(a0, a1, a2, a3, aAddr);
            LDSM4(a4, a5, a6, a7, aAddr + 16 * SX_SLOT);
            const uint32_t bAddr = sw + (uint32_t)(tap * (128 * SX_SLOT)) + laneB;
#pragma unroll
            for (int p = 0; p < 4; ++p) {
                uint32_t b0, b1, b2, b3;
                LDSM4(b0, b1, b2, b3, bAddr + p * (16 * SX_SLOT));
                MMA16816(acc[0][2 * p],     a0, a1, a2, a3, b0, b1);
                MMA16816(acc[0][2 * p + 1], a0, a1, a2, a3, b2, b3);
                MMA16816(acc[1][2 * p],     a4, a5, a6, a7, b0, b1);
                MMA16816(acc[1][2 * p + 1], a4, a5, a6, a7, b2, b3);
            }
        }
        // no trailing sync: next iteration writes the other buffer; the
        // pre-compute __syncthreads() provides the ordering.
    }

    __syncthreads();

    // ---- epilogue: acc -> SMEM transpose -> coalesced global stores ----
    float* s_out = reinterpret_cast<float*>(smem);
    {
        const int m0g = mw * 32 + (lane >> 2);
#pragma unroll
        for (int mt = 0; mt < 2; ++mt) {
            const int m0 = m0g + mt * 16;
#pragma unroll
            for (int nt = 0; nt < 8; ++nt) {
                const int co = nw * 64 + nt * 8 + (lane & 3) * 2;
                s_out[co * OUT_STR + m0]           = acc[mt][nt][0];
                s_out[(co + 1) * OUT_STR + m0]     = acc[mt][nt][1];
                s_out[co * OUT_STR + m0 + 8]       = acc[mt][nt][2];
                s_out[(co + 1) * OUT_STR + m0 + 8] = acc[mt][nt][3];
            }
        }
    }
    __syncthreads();
    {
        const int co = t >> 2;       // 0..127
        const int mq = t & 3;
        const float bi = bias[a * CH + co0 + co];
        float* og = out + ((size_t)(bb * CH + co0 + co) * HH + h0) * WW;
        const float* sr = &s_out[co * OUT_STR];
#pragma unroll
        for (int i = 0; i < 16; ++i) {
            const int m = mq * 4 + i * 16;
            float4 v = *reinterpret_cast<const float4*>(sr + m);
            v.x += bi; v.y += bi; v.z += bi; v.w += bi;
            *reinterpret_cast<float4*>(og + m) = v;
        }
    }
}

extern "C" void kernel_launch(void* const* d_in, const int* in_sizes, int n_in,
                              void* d_out, int out_size)
{
    const float* x    = (const float*)d_in[0];  // [64,256,32,32]
    const int*   arc  = (const int*)  d_in[1];  // [64]
    const float* Wt   = (const float*)d_in[2];  // [4,256,256,3,3]
    const float* bias = (const float*)d_in[3];  // [4,256]
    float* out = (float*)d_out;                 // [64,256,32,32]

    wt_transpose_kernel<<<1024, 256>>>(Wt);

    cudaFuncSetAttribute(conv_mma_kernel,
                         cudaFuncAttributeMaxDynamicSharedMemorySize, SMEM_TOTAL);
    dim3 grid(HH / SP_ROWS, CH / CO_TILE, BATCH);   // (4, 2, 64) = 512 CTAs
    conv_mma_kernel<<<grid, THREADS, SMEM_TOTAL>>>(x, arc, bias, out);
}

// round 7
// speedup vs baseline: 5.9608x; 1.8581x over previous
#include <cuda_runtime.h>
#include <cuda_fp16.h>
#include <cstdint>

#define BATCH   64
#define CH      256
#define HH      32
#define WW      32
#define NCHUNK  16        // 16 ci-chunks of 16
#define NSTAGE  3

#define THREADS 512
#define SP_ROWS 8         // M = 256 spatial (8 rows x 32 cols)
#define CO_TILE 128       // N

// SMEM stage layout
#define SX_SLOT   48                      // bytes per slot (16 ci fp16 in first 32B; 48 kills LDSM conflicts)
#define SX_BYTES  (10 * 34 * SX_SLOT)     // 16320
#define SW_BYTES  (9 * 128 * SX_SLOT)     // 55296
#define STAGE_BYTES (SX_BYTES + SW_BYTES) // 71616
#define SMEM_TOTAL  (NSTAGE * STAGE_BYTES)// 214848
#define OUT_STR   272                     // epilogue s_out stride (floats)

// Pre-transposed fp16 weights: [branch][ci_chunk 16][tap 9][co 256][ci16]
static __device__ __half g_wt[4u * 16 * 9 * 256 * 16];
// Pre-converted fp16 input: [b][h][w][ci]
static __device__ __half g_xh[(size_t)BATCH * HH * WW * CH];

static __device__ __forceinline__ uint32_t s2u(const void* p) {
    return (uint32_t)__cvta_generic_to_shared(p);
}

static __device__ __forceinline__ void cp16p(uint32_t dst, const void* src, int ok) {
    asm volatile(
        "{\n\t.reg .pred p;\n\t"
        "setp.ne.b32 p, %2, 0;\n\t"
        "@p  cp.async.cg.shared.global [%0], [%1], 16;\n\t"
        "@!p cp.async.cg.shared.global [%0], [%1], 16, 0;\n\t}"
        :: "r"(dst), "l"(src), "r"(ok) : "memory");
}
static __device__ __forceinline__ void cp16(uint32_t dst, const void* src) {
    asm volatile("cp.async.cg.shared.global [%0], [%1], 16;"
                 :: "r"(dst), "l"(src) : "memory");
}
#define CP_COMMIT() asm volatile("cp.async.commit_group;" ::: "memory")
#define CP_WAIT1()  asm volatile("cp.async.wait_group 1;" ::: "memory")

#define LDSM4(r0, r1, r2, r3, addr)                                         \
    asm volatile("ldmatrix.sync.aligned.m8n8.x4.shared.b16 "                \
                 "{%0,%1,%2,%3}, [%4];"                                     \
                 : "=r"(r0), "=r"(r1), "=r"(r2), "=r"(r3) : "r"(addr))

#define MMA16816(c, a0, a1, a2, a3, b0, b1)                                 \
    asm volatile("mma.sync.aligned.m16n8k16.row.col.f32.f16.f16.f32 "       \
                 "{%0,%1,%2,%3}, {%4,%5,%6,%7}, {%8,%9}, {%0,%1,%2,%3};"    \
                 : "+f"((c)[0]), "+f"((c)[1]), "+f"((c)[2]), "+f"((c)[3])   \
                 : "r"(a0), "r"(a1), "r"(a2), "r"(a3), "r"(b0), "r"(b1))

// ---------------------------------------------------------------------------
// W[a][co][ci][tap] fp32 -> g_wt[a][ci>>4][tap][co][ci&15] fp16
// ---------------------------------------------------------------------------
__global__ __launch_bounds__(256)
void wt_transpose_kernel(const float* __restrict__ Wt)
{
    const int tid = blockIdx.x * 256 + threadIdx.x;   // 262144 total
    const int a   = tid >> 16;
    const int co  = (tid >> 8) & 255;
    const int ci  = tid & 255;
    const float* src = Wt + ((size_t)(a * 256 + co) * 256 + ci) * 9;
    const int kc   = ci >> 4;
    const int ci16 = ci & 15;
#pragma unroll
    for (int tap = 0; tap < 9; ++tap) {
        g_wt[((((size_t)a * 16 + kc) * 9 + tap) * 256 + co) * 16 + ci16] =
            __float2half_rn(src[tap]);
    }
}

// ---------------------------------------------------------------------------
// x[b][ci][h][w] fp32 -> g_xh[b][h][w][ci] fp16 (smem tile transpose)
// ---------------------------------------------------------------------------
__global__ __launch_bounds__(256)
void x_transpose_kernel(const float* __restrict__ x)
{
    __shared__ float tile[256 * 33];
    const int bb = blockIdx.x, h = blockIdx.y, t = threadIdx.x;
    const int tw = t & 31, tc = t >> 5;
    const float* src = x + (size_t)bb * 256 * (HH * WW) + h * WW;
#pragma unroll
    for (int p = 0; p < 32; ++p) {
        const int ci = p * 8 + tc;
        tile[ci * 33 + tw] = src[(size_t)ci * (HH * WW) + tw];
    }
    __syncthreads();
    __half* dst = g_xh + (size_t)(bb * HH + h) * WW * 256;
#pragma unroll
    for (int w = 0; w < 32; ++w)
        dst[w * 256 + t] = __float2half_rn(tile[t * 33 + w]);
}

// ---------------------------------------------------------------------------
// Main kernel: tap-decomposed fp16 HMMA conv, 3-stage cp.async pipeline
// ---------------------------------------------------------------------------
__global__ __launch_bounds__(THREADS, 1)
void conv_mma_kernel(const int*   __restrict__ arc,
                     const float* __restrict__ bias,
                     float*       __restrict__ out)
{
    extern __shared__ __align__(16) char smem[];

    const int t    = threadIdx.x;
    const int lane = t & 31;
    const int wid  = t >> 5;          // 0..15
    const int mw   = wid >> 1;        // 0..7  (spatial row)
    const int nw   = wid & 1;         // 0..1  (co half)

    const int bb  = blockIdx.z;
    const int co0 = blockIdx.y * CO_TILE;
    const int h0  = blockIdx.x * SP_ROWS;
    const int a   = arc[bb];

    const uint32_t smem_u = s2u(smem);

    float acc[2][8][4];
#pragma unroll
    for (int mt = 0; mt < 2; ++mt)
#pragma unroll
        for (int nt = 0; nt < 8; ++nt)
#pragma unroll
            for (int k = 0; k < 4; ++k)
                acc[mt][nt][k] = 0.0f;

    // ---- per-thread staging addresses (constant across chunks up to +offset) ----
    // X: thread t < 340 owns slot t (one 32B ci-run = 2x cp.async 16B)
    int xok = 0; const __half* xsrc = g_xh; uint32_t xdst = 0;
    if (t < 340) {
        const int row = t / 34, col = t - 34 * row;
        const int gr = h0 + row - 1, gc = col - 1;
        xok = ((unsigned)gr < (unsigned)HH) && ((unsigned)gc < (unsigned)WW);
        if (xok) xsrc = g_xh + (size_t)((bb * HH + gr) * WW + gc) * 256;
        xdst = (uint32_t)(t * SX_SLOT);
    }
    // W: thread owns slots t, t+512, and t+1024 if t<128 (2x 16B each)
    const __half* wbase = g_wt + (size_t)a * (16 * 9 * 256 * 16);
    const int ws0 = t, ws1 = t + 512, ws2 = t + 1024;
    const size_t wsrc0 = ((size_t)(ws0 >> 7) * 256 + co0 + (ws0 & 127)) * 16;
    const size_t wsrc1 = ((size_t)(ws1 >> 7) * 256 + co0 + (ws1 & 127)) * 16;
    const size_t wsrc2 = ((size_t)(ws2 >> 7) * 256 + co0 + (ws2 & 127)) * 16;
    const uint32_t wdst0 = (uint32_t)(SX_BYTES + ws0 * SX_SLOT);
    const uint32_t wdst1 = (uint32_t)(SX_BYTES + ws1 * SX_SLOT);
    const uint32_t wdst2 = (uint32_t)(SX_BYTES + ws2 * SX_SLOT);

    // per-lane ldmatrix offsets
    const uint32_t laneA = (uint32_t)((lane & 15) * SX_SLOT + (lane >> 4) * 16);
    const uint32_t laneB = (uint32_t)(((((lane >> 4) & 1) * 8 + (lane & 7)) + nw * 64) * SX_SLOT
                                      + ((lane >> 3) & 1) * 16);

    // ---- prefetch helper (chunk it -> stage it % NSTAGE) ----
    auto prefetch = [&](int it) {
        const uint32_t st = smem_u + (uint32_t)((it % NSTAGE) * STAGE_BYTES);
        if (t < 340) {
            const __half* s = xsrc + it * 16;
            cp16p(st + xdst,      s,     xok);
            cp16p(st + xdst + 16, s + 8, xok);
        }
        const __half* wc = wbase + (size_t)it * (9 * 256 * 16);
        cp16(st + wdst0,      wc + wsrc0);
        cp16(st + wdst0 + 16, wc + wsrc0 + 8);
        cp16(st + wdst1,      wc + wsrc1);
        cp16(st + wdst1 + 16, wc + wsrc1 + 8);
        if (t < 128) {
            cp16(st + wdst2,      wc + wsrc2);
            cp16(st + wdst2 + 16, wc + wsrc2 + 8);
        }
    };

    prefetch(0); CP_COMMIT();
    prefetch(1); CP_COMMIT();

    for (int it = 0; it < NCHUNK; ++it) {
        CP_WAIT1();
        __syncthreads();
        if (it + 2 < NCHUNK) prefetch(it + 2);
        CP_COMMIT();                       // empty group when no prefetch: keeps accounting uniform

        const uint32_t stBase = (uint32_t)((it % NSTAGE) * STAGE_BYTES);
        const uint32_t sx = smem_u + stBase;
        const uint32_t sw = smem_u + stBase + SX_BYTES;
#pragma unroll
        for (int tap = 0; tap < 9; ++tap) {
            const int dh = tap / 3;
            const int dw = tap - 3 * dh;
            const uint32_t aAddr = sx + (uint32_t)(((mw + dh) * 34 + dw) * SX_SLOT) + laneA;
            uint32_t a0, a1, a2, a3, a4, a5, a6, a7;
            LDSM4(a0, a1, a2, a3, aAddr);
            LDSM4(a4, a5, a6, a7, aAddr + 16 * SX_SLOT);
            const uint32_t bAddr = sw + (uint32_t)(tap * (128 * SX_SLOT)) + laneB;
#pragma unroll
            for (int p = 0; p < 4; ++p) {
                uint32_t b0, b1, b2, b3;
                LDSM4(b0, b1, b2, b3, bAddr + p * (16 * SX_SLOT));
                MMA16816(acc[0][2 * p],     a0, a1, a2, a3, b0, b1);
                MMA16816(acc[0][2 * p + 1], a0, a1, a2, a3, b2, b3);
                MMA16816(acc[1][2 * p],     a4, a5, a6, a7, b0, b1);
                MMA16816(acc[1][2 * p + 1], a4, a5, a6, a7, b2, b3);
            }
        }
    }

    __syncthreads();

    // ---- epilogue: acc -> SMEM transpose -> coalesced global stores ----
    float* s_out = reinterpret_cast<float*>(smem);
    {
        const int m0g = mw * 32 + (lane >> 2);
#pragma unroll
        for (int mt = 0; mt < 2; ++mt) {
            const int m0 = m0g + mt * 16;
#pragma unroll
            for (int nt = 0; nt < 8; ++nt) {
                const int co = nw * 64 + nt * 8 + (lane & 3) * 2;
                s_out[co * OUT_STR + m0]           = acc[mt][nt][0];
                s_out[(co + 1) * OUT_STR + m0]     = acc[mt][nt][1];
                s_out[co * OUT_STR + m0 + 8]       = acc[mt][nt][2];
                s_out[(co + 1) * OUT_STR + m0 + 8] = acc[mt][nt][3];
            }
        }
    }
    __syncthreads();
    {
        const int co = t >> 2;       // 0..127
        const int mq = t & 3;
        const float bi = bias[a * CH + co0 + co];
        float* og = out + ((size_t)(bb * CH + co0 + co) * HH + h0) * WW;
        const float* sr = &s_out[co * OUT_STR];
#pragma unroll
        for (int i = 0; i < 16; ++i) {
            const int m = mq * 4 + i * 16;
            float4 v = *reinterpret_cast<const float4*>(sr + m);
            v.x += bi; v.y += bi; v.z += bi; v.w += bi;
            *reinterpret_cast<float4*>(og + m) = v;
        }
    }
}

extern "C" void kernel_launch(void* const* d_in, const int* in_sizes, int n_in,
                              void* d_out, int out_size)
{
    const float* x    = (const float*)d_in[0];  // [64,256,32,32]
    const int*   arc  = (const int*)  d_in[1];  // [64]
    const float* Wt   = (const float*)d_in[2];  // [4,256,256,3,3]
    const float* bias = (const float*)d_in[3];  // [4,256]
    float* out = (float*)d_out;                 // [64,256,32,32]

    wt_transpose_kernel<<<1024, 256>>>(Wt);
    x_transpose_kernel<<<dim3(BATCH, HH), 256>>>(x);

    cudaFuncSetAttribute(conv_mma_kernel,
                         cudaFuncAttributeMaxDynamicSharedMemorySize, SMEM_TOTAL);
    dim3 grid(HH / SP_ROWS, CH / CO_TILE, BATCH);   // (4, 2, 64) = 512 CTAs
    conv_mma_kernel<<<grid, THREADS, SMEM_TOTAL>>>(arc, bias, out);
}